// round 12
// baseline (speedup 1.0000x reference)
#include <cuda_runtime.h>

// BaseEBM: 1M samples x 20 GD steps on y through fixed 2->32->32->32->1
// ReLU MLP. R12 = R11 + software pipelining: row loops at "#pragma unroll 2"
// so ptxas can front-load the next row's 8x LDS.128 behind the current row's
// 32x FFMA2 (R11 profile: fma=67%/L1=67%/issue=61% -- pure LDS->FMA
// dependency stall, NOT occupancy: 12->16 warps bought only 1.5%).
// Register budget widened to fit the 2-row window: __launch_bounds__(128,3)
// -> 170-reg cap for a ~140-reg demand. Two NAMED u64 accumulator banks
// (A=sample0, C=sample1), shared-scratch handoffs, dynamic smem 49920B.

#define W 32
#define INNER_STEPS 20
#define INNER_LR 0.1f
#define TPB 128

using u64 = unsigned long long;

// dynamic smem layout (bytes):
//   [0      : 16384)  s_fw1|s_fw2|s_bw2|s_bw1  (4 x 1024 floats)
//   [16384  : 17152)  s_w0x|s_w0y|s_b0|s_b1|s_b2|s_w3 (6 x 32 floats)
//   [17152  : 49920)  scr: u64[32 * TPB]
#define SMEM_FW1   0
#define SMEM_FW2   (1024 * 4)
#define SMEM_BW2   (2048 * 4)
#define SMEM_BW1   (3072 * 4)
#define SMEM_SML   (4096 * 4)
#define SMEM_SCR   17152
#define SMEM_TOTAL (SMEM_SCR + W * TPB * 8)

__device__ __forceinline__ u64 fma2(u64 a, u64 b, u64 c) {
    u64 d;
    asm("fma.rn.f32x2 %0, %1, %2, %3;" : "=l"(d) : "l"(a), "l"(b), "l"(c));
    return d;
}
__device__ __forceinline__ u64 dup2(float x) {
    u64 d;
    asm("mov.b64 %0, {%1, %1};" : "=l"(d) : "f"(x));
    return d;
}
__device__ __forceinline__ u64 pack2(float lo, float hi) {
    u64 d;
    asm("mov.b64 %0, {%1, %2};" : "=l"(d) : "f"(lo), "f"(hi));
    return d;
}
__device__ __forceinline__ void unpk(u64 v, float& lo, float& hi) {
    asm("mov.b64 {%0, %1}, %2;" : "=f"(lo), "=f"(hi) : "l"(v));
}

#define APPLY16(M) M(0) M(1) M(2) M(3) M(4) M(5) M(6) M(7) \
                   M(8) M(9) M(10) M(11) M(12) M(13) M(14) M(15)

// A0..A15 += D0 * row[pair]; C0..C15 += D1 * row[pair]. 8x LDS.128, 32x FFMA2.
#define ROWFMA2(ROW, D0, D1) do {                                          \
    const ulonglong2* _r = reinterpret_cast<const ulonglong2*>(ROW);       \
    {                                                                      \
        ulonglong2 _wa = _r[0], _wb = _r[1], _wc = _r[2], _wd = _r[3];     \
        A0 = fma2(_wa.x, D0, A0); C0 = fma2(_wa.x, D1, C0);                \
        A1 = fma2(_wa.y, D0, A1); C1 = fma2(_wa.y, D1, C1);                \
        A2 = fma2(_wb.x, D0, A2); C2 = fma2(_wb.x, D1, C2);                \
        A3 = fma2(_wb.y, D0, A3); C3 = fma2(_wb.y, D1, C3);                \
        A4 = fma2(_wc.x, D0, A4); C4 = fma2(_wc.x, D1, C4);                \
        A5 = fma2(_wc.y, D0, A5); C5 = fma2(_wc.y, D1, C5);                \
        A6 = fma2(_wd.x, D0, A6); C6 = fma2(_wd.x, D1, C6);                \
        A7 = fma2(_wd.y, D0, A7); C7 = fma2(_wd.y, D1, C7);                \
    }                                                                      \
    {                                                                      \
        ulonglong2 _wa = _r[4], _wb = _r[5], _wc = _r[6], _wd = _r[7];     \
        A8  = fma2(_wa.x, D0, A8 ); C8  = fma2(_wa.x, D1, C8 );            \
        A9  = fma2(_wa.y, D0, A9 ); C9  = fma2(_wa.y, D1, C9 );            \
        A10 = fma2(_wb.x, D0, A10); C10 = fma2(_wb.x, D1, C10);            \
        A11 = fma2(_wb.y, D0, A11); C11 = fma2(_wb.y, D1, C11);            \
        A12 = fma2(_wc.x, D0, A12); C12 = fma2(_wc.x, D1, C12);            \
        A13 = fma2(_wc.y, D0, A13); C13 = fma2(_wc.y, D1, C13);            \
        A14 = fma2(_wd.x, D0, A14); C14 = fma2(_wd.x, D1, C14);            \
        A15 = fma2(_wd.y, D0, A15); C15 = fma2(_wd.y, D1, C15);            \
    }                                                                      \
} while (0)

__global__ __launch_bounds__(TPB, 3) void BaseEBM_kernel(
    const float* __restrict__ gX,
    const float* __restrict__ gW0,   // [32,2]
    const float* __restrict__ gB0,   // [32]
    const float* __restrict__ gW1,   // [32,32]
    const float* __restrict__ gB1,   // [32]
    const float* __restrict__ gW2,   // [32,32]
    const float* __restrict__ gB2,   // [32]
    const float* __restrict__ gW3,   // [32]
    const float* __restrict__ gYM,   // [1]
    float* __restrict__ gOUT,
    int n) {
    extern __shared__ char dsm[];
    float* s_fw1 = reinterpret_cast<float*>(dsm + SMEM_FW1);  // fw1[i*32+j]=W1[j][i]
    float* s_fw2 = reinterpret_cast<float*>(dsm + SMEM_FW2);  // fw2[i*32+j]=W2[j][i]
    float* s_bw2 = reinterpret_cast<float*>(dsm + SMEM_BW2);  // bw2[i*32+j]=W2[i][j]
    float* s_bw1 = reinterpret_cast<float*>(dsm + SMEM_BW1);  // bw1[i*32+j]=W1[i][j]
    float* s_w0x = reinterpret_cast<float*>(dsm + SMEM_SML);
    float* s_w0y = s_w0x + W;
    float* s_b0  = s_w0y + W;
    float* s_b1  = s_b0 + W;
    float* s_b2  = s_b1 + W;
    float* s_w3  = s_b2 + W;
    u64*   scr   = reinterpret_cast<u64*>(dsm + SMEM_SCR);

    const int tid = threadIdx.x;
#pragma unroll
    for (int k = 0; k < (W * W) / TPB; k++) {
        int e = k * TPB + tid;
        int i = e >> 5, j = e & 31;
        s_fw1[e] = gW1[j * W + i];
        s_fw2[e] = gW2[j * W + i];
        s_bw2[e] = gW2[e];
        s_bw1[e] = gW1[e];
    }
    if (tid < W) {
        s_w0x[tid] = gW0[2 * tid + 0];
        s_w0y[tid] = gW0[2 * tid + 1];
        s_b0[tid]  = gB0[tid];
        s_b1[tid]  = gB1[tid];
        s_b2[tid]  = gB2[tid];
        s_w3[tid]  = gW3[tid];
    }
    __syncthreads();

    const int s0 = blockIdx.x * (2 * TPB) + tid;
    const int s1 = s0 + TPB;
    if (s0 >= n) return;

    const float x0 = gX[s0];
    const float x1 = (s1 < n) ? gX[s1] : 0.0f;
    float y0 = gYM[0];
    float y1 = y0;

    const u64* b1p = reinterpret_cast<const u64*>(s_b1);
    const u64* b2p = reinterpret_cast<const u64*>(s_b2);
    u64* pS = scr + tid;

    u64 A0, A1, A2, A3, A4, A5, A6, A7;
    u64 A8, A9, A10, A11, A12, A13, A14, A15;
    u64 C0, C1, C2, C3, C4, C5, C6, C7;
    u64 C8, C9, C10, C11, C12, C13, C14, C15;

#pragma unroll 1
    for (int s = 0; s < INNER_STEPS; s++) {
        unsigned m0a = 0u, m0b = 0u, m1a = 0u, m1b = 0u, m2a = 0u, m2b = 0u;

        // ---- matvec 1: acc = b1 + fw1^T relu(pre0)
#define INIT_B1(p) { u64 _b = b1p[p]; A##p = _b; C##p = _b; }
        APPLY16(INIT_B1)
#undef INIT_B1
#pragma unroll 2
        for (int i = 0; i < W; i++) {
            float wx = s_w0x[i], wy = s_w0y[i], b = s_b0[i];
            float pa = fmaf(y0, wy, fmaf(x0, wx, b));
            float pb = fmaf(y1, wy, fmaf(x1, wx, b));
            m0a |= (pa > 0.0f) ? (1u << i) : 0u;
            m0b |= (pb > 0.0f) ? (1u << i) : 0u;
            u64 d0 = dup2(fmaxf(pa, 0.0f));
            u64 d1 = dup2(fmaxf(pb, 0.0f));
            ROWFMA2(s_fw1 + i * 32, d0, d1);
        }

        // ---- acc = pre1. h1 = relu -> scratch; m1 recorded.
#define ST_H1(p) {                                                         \
        float _al, _ah, _cl, _ch;                                          \
        unpk(A##p, _al, _ah); unpk(C##p, _cl, _ch);                        \
        m1a |= (_al > 0.0f) ? (1u << (2 * p))     : 0u;                    \
        m1a |= (_ah > 0.0f) ? (1u << (2 * p + 1)) : 0u;                    \
        m1b |= (_cl > 0.0f) ? (1u << (2 * p))     : 0u;                    \
        m1b |= (_ch > 0.0f) ? (1u << (2 * p + 1)) : 0u;                    \
        pS[(2 * p) * TPB]     = pack2(fmaxf(_al, 0.0f), fmaxf(_cl, 0.0f)); \
        pS[(2 * p + 1) * TPB] = pack2(fmaxf(_ah, 0.0f), fmaxf(_ch, 0.0f)); }
        APPLY16(ST_H1)
#undef ST_H1

        // ---- matvec 2: acc = b2 + fw2^T h1(scratch)
#define INIT_B2(p) { u64 _b = b2p[p]; A##p = _b; C##p = _b; }
        APPLY16(INIT_B2)
#undef INIT_B2
#pragma unroll 2
        for (int i = 0; i < W; i++) {
            float v0, v1;
            unpk(pS[i * TPB], v0, v1);
            u64 d0 = dup2(v0), d1 = dup2(v1);
            ROWFMA2(s_fw2 + i * 32, d0, d1);
        }

        // ---- acc = pre2. Record sign masks only (g2 = m2 ? w3 : 0).
#define ST_M2(p) {                                                         \
        float _al, _ah, _cl, _ch;                                          \
        unpk(A##p, _al, _ah); unpk(C##p, _cl, _ch);                        \
        m2a |= (_al > 0.0f) ? (1u << (2 * p))     : 0u;                    \
        m2a |= (_ah > 0.0f) ? (1u << (2 * p + 1)) : 0u;                    \
        m2b |= (_cl > 0.0f) ? (1u << (2 * p))     : 0u;                    \
        m2b |= (_ch > 0.0f) ? (1u << (2 * p + 1)) : 0u; }
        APPLY16(ST_M2)
#undef ST_M2

        // ---- matvec 3 (backward): acc = bw2^T (m2-masked w3)
#define ZERO_AC(p) { A##p = 0ull; C##p = 0ull; }
        APPLY16(ZERO_AC)
#pragma unroll 2
        for (int i = 0; i < W; i++) {
            float w3i = s_w3[i];
            float ga = ((m2a >> i) & 1u) ? w3i : 0.0f;
            float gb = ((m2b >> i) & 1u) ? w3i : 0.0f;
            u64 d0 = dup2(ga), d1 = dup2(gb);
            ROWFMA2(s_bw2 + i * 32, d0, d1);
        }

        // ---- acc = g1raw. g1 = m1-masked -> scratch.
#define ST_G1(p) {                                                         \
        float _al, _ah, _cl, _ch;                                          \
        unpk(A##p, _al, _ah); unpk(C##p, _cl, _ch);                        \
        pS[(2 * p) * TPB]     = pack2((m1a & (1u << (2 * p)))     ? _al : 0.0f, \
                                      (m1b & (1u << (2 * p)))     ? _cl : 0.0f); \
        pS[(2 * p + 1) * TPB] = pack2((m1a & (1u << (2 * p + 1))) ? _ah : 0.0f, \
                                      (m1b & (1u << (2 * p + 1))) ? _ch : 0.0f); }
        APPLY16(ST_G1)
#undef ST_G1

        // ---- matvec 4 (backward): acc = bw1^T g1(scratch)
        APPLY16(ZERO_AC)
#undef ZERO_AC
#pragma unroll 2
        for (int i = 0; i < W; i++) {
            float v0, v1;
            unpk(pS[i * TPB], v0, v1);
            u64 d0 = dup2(v0), d1 = dup2(v1);
            ROWFMA2(s_bw1 + i * 32, d0, d1);
        }

        // ---- dy = sum_k (pre0_k>0 ? w0y_k : 0) * g0raw_k
        float dy0 = 0.0f, dy1 = 0.0f;
#define DYM(p) {                                                           \
        float _al, _ah, _cl, _ch;                                          \
        unpk(A##p, _al, _ah); unpk(C##p, _cl, _ch);                        \
        float _wl = s_w0y[2 * p], _wh = s_w0y[2 * p + 1];                  \
        dy0 = fmaf((m0a & (1u << (2 * p)))     ? _wl : 0.0f, _al, dy0);    \
        dy0 = fmaf((m0a & (1u << (2 * p + 1))) ? _wh : 0.0f, _ah, dy0);    \
        dy1 = fmaf((m0b & (1u << (2 * p)))     ? _wl : 0.0f, _cl, dy1);    \
        dy1 = fmaf((m0b & (1u << (2 * p + 1))) ? _wh : 0.0f, _ch, dy1); }
        APPLY16(DYM)
#undef DYM

        y0 = fmaf(-INNER_LR, dy0, y0);
        y1 = fmaf(-INNER_LR, dy1, y1);
    }

    gOUT[s0] = y0;
    if (s1 < n) gOUT[s1] = y1;
}

extern "C" void kernel_launch(void* const* d_in, const int* in_sizes, int n_in,
                              void* d_out, int out_size) {
    const float* x  = (const float*)d_in[0];
    const float* w0 = (const float*)d_in[1];
    const float* b0 = (const float*)d_in[2];
    const float* w1 = (const float*)d_in[3];
    const float* b1 = (const float*)d_in[4];
    const float* w2 = (const float*)d_in[5];
    const float* b2 = (const float*)d_in[6];
    const float* w3 = (const float*)d_in[7];
    const float* ymean = (const float*)d_in[9];  // d_in[8] = b3 (unused)
    float* out = (float*)d_out;

    cudaFuncSetAttribute(BaseEBM_kernel,
                         cudaFuncAttributeMaxDynamicSharedMemorySize,
                         SMEM_TOTAL);

    int n = in_sizes[0];
    int blocks = (n + 2 * TPB - 1) / (2 * TPB);
    BaseEBM_kernel<<<blocks, TPB, SMEM_TOTAL>>>(x, w0, b0, w1, b1, w2, b2, w3,
                                                ymean, out, n);
}

// round 13
// speedup vs baseline: 1.1028x; 1.1028x over previous
#include <cuda_runtime.h>

// BaseEBM: 1M samples x 20 GD steps on y through fixed 2->32->32->32->1
// ReLU MLP. R13 = R11 + CONSTANT-PORT OFFLOAD: measured model shows the
// smem crossbar (LDS.128 broadcast ~2 SM-cyc, shared by 4 SMSPs) and the
// fma pipe are exactly co-saturated at 4.3e6 cyc each. The two BACKWARD
// matrices are consumed in NATURAL layout -> copy verbatim into
// __constant__ (cudaMemcpyToSymbolAsync, graph-capturable D2D) and read
// them through the separate constant port (uniform index -> LDCU path).
// Halves LDS wavefronts; forward matvecs keep smem. Everything else is
// the proven R11 structure (2 samples/thread, f32x2, named u64 banks,
// real row loops, 128-reg cap, 16 warps/SM).

#define W 32
#define INNER_STEPS 20
#define INNER_LR 0.1f
#define TPB 128

using u64 = unsigned long long;

__constant__ float cBW2[W * W];   // W2 natural: cBW2[i*32+j] = W2[i][j]
__constant__ float cBW1[W * W];   // W1 natural: cBW1[i*32+j] = W1[i][j]

__device__ __forceinline__ u64 fma2(u64 a, u64 b, u64 c) {
    u64 d;
    asm("fma.rn.f32x2 %0, %1, %2, %3;" : "=l"(d) : "l"(a), "l"(b), "l"(c));
    return d;
}
__device__ __forceinline__ u64 dup2(float x) {
    u64 d;
    asm("mov.b64 %0, {%1, %1};" : "=l"(d) : "f"(x));
    return d;
}
__device__ __forceinline__ u64 pack2(float lo, float hi) {
    u64 d;
    asm("mov.b64 %0, {%1, %2};" : "=l"(d) : "f"(lo), "f"(hi));
    return d;
}
__device__ __forceinline__ void unpk(u64 v, float& lo, float& hi) {
    asm("mov.b64 {%0, %1}, %2;" : "=f"(lo), "=f"(hi) : "l"(v));
}

#define APPLY16(M) M(0) M(1) M(2) M(3) M(4) M(5) M(6) M(7) \
                   M(8) M(9) M(10) M(11) M(12) M(13) M(14) M(15)

// A0..A15 += D0 * row[pair]; C0..C15 += D1 * row[pair]. Works for smem or
// constant ROW pointers (address space inferred by the compiler).
#define ROWFMA2(ROW, D0, D1) do {                                          \
    const ulonglong2* _r = reinterpret_cast<const ulonglong2*>(ROW);       \
    {                                                                      \
        ulonglong2 _wa = _r[0], _wb = _r[1], _wc = _r[2], _wd = _r[3];     \
        A0 = fma2(_wa.x, D0, A0); C0 = fma2(_wa.x, D1, C0);                \
        A1 = fma2(_wa.y, D0, A1); C1 = fma2(_wa.y, D1, C1);                \
        A2 = fma2(_wb.x, D0, A2); C2 = fma2(_wb.x, D1, C2);                \
        A3 = fma2(_wb.y, D0, A3); C3 = fma2(_wb.y, D1, C3);                \
        A4 = fma2(_wc.x, D0, A4); C4 = fma2(_wc.x, D1, C4);                \
        A5 = fma2(_wc.y, D0, A5); C5 = fma2(_wc.y, D1, C5);                \
        A6 = fma2(_wd.x, D0, A6); C6 = fma2(_wd.x, D1, C6);                \
        A7 = fma2(_wd.y, D0, A7); C7 = fma2(_wd.y, D1, C7);                \
    }                                                                      \
    {                                                                      \
        ulonglong2 _wa = _r[4], _wb = _r[5], _wc = _r[6], _wd = _r[7];     \
        A8  = fma2(_wa.x, D0, A8 ); C8  = fma2(_wa.x, D1, C8 );            \
        A9  = fma2(_wa.y, D0, A9 ); C9  = fma2(_wa.y, D1, C9 );            \
        A10 = fma2(_wb.x, D0, A10); C10 = fma2(_wb.x, D1, C10);            \
        A11 = fma2(_wb.y, D0, A11); C11 = fma2(_wb.y, D1, C11);            \
        A12 = fma2(_wc.x, D0, A12); C12 = fma2(_wc.x, D1, C12);            \
        A13 = fma2(_wc.y, D0, A13); C13 = fma2(_wc.y, D1, C13);            \
        A14 = fma2(_wd.x, D0, A14); C14 = fma2(_wd.x, D1, C14);            \
        A15 = fma2(_wd.y, D0, A15); C15 = fma2(_wd.y, D1, C15);            \
    }                                                                      \
} while (0)

__global__ __launch_bounds__(TPB, 4) void BaseEBM_kernel(
    const float* __restrict__ gX,
    const float* __restrict__ gW0,   // [32,2]
    const float* __restrict__ gB0,   // [32]
    const float* __restrict__ gW1,   // [32,32]
    const float* __restrict__ gB1,   // [32]
    const float* __restrict__ gW2,   // [32,32]
    const float* __restrict__ gB2,   // [32]
    const float* __restrict__ gW3,   // [32]
    const float* __restrict__ gYM,   // [1]
    float* __restrict__ gOUT,
    int n) {
    __shared__ alignas(16) float s_fw1[W * W];   // fw1[i*32+j] = W1[j][i]
    __shared__ alignas(16) float s_fw2[W * W];   // fw2[i*32+j] = W2[j][i]
    __shared__ alignas(16) float s_w0x[W];
    __shared__ alignas(16) float s_w0y[W];
    __shared__ alignas(16) float s_b0[W];
    __shared__ alignas(16) float s_b1[W];
    __shared__ alignas(16) float s_b2[W];
    __shared__ alignas(16) float s_w3[W];
    __shared__ alignas(16) u64 scr[W * TPB];  // per-thread col; 2 samples packed

    const int tid = threadIdx.x;
#pragma unroll
    for (int k = 0; k < (W * W) / TPB; k++) {
        int e = k * TPB + tid;
        int i = e >> 5, j = e & 31;
        s_fw1[e] = gW1[j * W + i];
        s_fw2[e] = gW2[j * W + i];
    }
    if (tid < W) {
        s_w0x[tid] = gW0[2 * tid + 0];
        s_w0y[tid] = gW0[2 * tid + 1];
        s_b0[tid]  = gB0[tid];
        s_b1[tid]  = gB1[tid];
        s_b2[tid]  = gB2[tid];
        s_w3[tid]  = gW3[tid];
    }
    __syncthreads();

    const int s0 = blockIdx.x * (2 * TPB) + tid;
    const int s1 = s0 + TPB;
    if (s0 >= n) return;

    const float x0 = gX[s0];
    const float x1 = (s1 < n) ? gX[s1] : 0.0f;
    float y0 = gYM[0];
    float y1 = y0;

    const u64* b1p = reinterpret_cast<const u64*>(s_b1);
    const u64* b2p = reinterpret_cast<const u64*>(s_b2);
    u64* pS = scr + tid;

    u64 A0, A1, A2, A3, A4, A5, A6, A7;
    u64 A8, A9, A10, A11, A12, A13, A14, A15;
    u64 C0, C1, C2, C3, C4, C5, C6, C7;
    u64 C8, C9, C10, C11, C12, C13, C14, C15;

#pragma unroll 1
    for (int s = 0; s < INNER_STEPS; s++) {
        unsigned m0a = 0u, m0b = 0u, m1a = 0u, m1b = 0u, m2a = 0u, m2b = 0u;

        // ---- matvec 1 (smem): acc = b1 + fw1^T relu(pre0)
#define INIT_B1(p) { u64 _b = b1p[p]; A##p = _b; C##p = _b; }
        APPLY16(INIT_B1)
#undef INIT_B1
#pragma unroll 1
        for (int i = 0; i < W; i++) {
            float wx = s_w0x[i], wy = s_w0y[i], b = s_b0[i];
            float pa = fmaf(y0, wy, fmaf(x0, wx, b));
            float pb = fmaf(y1, wy, fmaf(x1, wx, b));
            m0a |= (pa > 0.0f) ? (1u << i) : 0u;
            m0b |= (pb > 0.0f) ? (1u << i) : 0u;
            u64 d0 = dup2(fmaxf(pa, 0.0f));
            u64 d1 = dup2(fmaxf(pb, 0.0f));
            ROWFMA2(s_fw1 + i * 32, d0, d1);
        }

        // ---- acc = pre1. h1 = relu -> scratch; m1 recorded.
#define ST_H1(p) {                                                         \
        float _al, _ah, _cl, _ch;                                          \
        unpk(A##p, _al, _ah); unpk(C##p, _cl, _ch);                        \
        m1a |= (_al > 0.0f) ? (1u << (2 * p))     : 0u;                    \
        m1a |= (_ah > 0.0f) ? (1u << (2 * p + 1)) : 0u;                    \
        m1b |= (_cl > 0.0f) ? (1u << (2 * p))     : 0u;                    \
        m1b |= (_ch > 0.0f) ? (1u << (2 * p + 1)) : 0u;                    \
        pS[(2 * p) * TPB]     = pack2(fmaxf(_al, 0.0f), fmaxf(_cl, 0.0f)); \
        pS[(2 * p + 1) * TPB] = pack2(fmaxf(_ah, 0.0f), fmaxf(_ch, 0.0f)); }
        APPLY16(ST_H1)
#undef ST_H1

        // ---- matvec 2 (smem): acc = b2 + fw2^T h1(scratch)
#define INIT_B2(p) { u64 _b = b2p[p]; A##p = _b; C##p = _b; }
        APPLY16(INIT_B2)
#undef INIT_B2
#pragma unroll 1
        for (int i = 0; i < W; i++) {
            float v0, v1;
            unpk(pS[i * TPB], v0, v1);
            u64 d0 = dup2(v0), d1 = dup2(v1);
            ROWFMA2(s_fw2 + i * 32, d0, d1);
        }

        // ---- acc = pre2. Record sign masks only (g2 = m2 ? w3 : 0).
#define ST_M2(p) {                                                         \
        float _al, _ah, _cl, _ch;                                          \
        unpk(A##p, _al, _ah); unpk(C##p, _cl, _ch);                        \
        m2a |= (_al > 0.0f) ? (1u << (2 * p))     : 0u;                    \
        m2a |= (_ah > 0.0f) ? (1u << (2 * p + 1)) : 0u;                    \
        m2b |= (_cl > 0.0f) ? (1u << (2 * p))     : 0u;                    \
        m2b |= (_ch > 0.0f) ? (1u << (2 * p + 1)) : 0u; }
        APPLY16(ST_M2)
#undef ST_M2

        // ---- matvec 3 (CONSTANT): acc = bw2^T (m2-masked w3)
#define ZERO_AC(p) { A##p = 0ull; C##p = 0ull; }
        APPLY16(ZERO_AC)
#pragma unroll 1
        for (int i = 0; i < W; i++) {
            float w3i = s_w3[i];
            float ga = ((m2a >> i) & 1u) ? w3i : 0.0f;
            float gb = ((m2b >> i) & 1u) ? w3i : 0.0f;
            u64 d0 = dup2(ga), d1 = dup2(gb);
            ROWFMA2(cBW2 + i * 32, d0, d1);
        }

        // ---- acc = g1raw. g1 = m1-masked -> scratch.
#define ST_G1(p) {                                                         \
        float _al, _ah, _cl, _ch;                                          \
        unpk(A##p, _al, _ah); unpk(C##p, _cl, _ch);                        \
        pS[(2 * p) * TPB]     = pack2((m1a & (1u << (2 * p)))     ? _al : 0.0f, \
                                      (m1b & (1u << (2 * p)))     ? _cl : 0.0f); \
        pS[(2 * p + 1) * TPB] = pack2((m1a & (1u << (2 * p + 1))) ? _ah : 0.0f, \
                                      (m1b & (1u << (2 * p + 1))) ? _ch : 0.0f); }
        APPLY16(ST_G1)
#undef ST_G1

        // ---- matvec 4 (CONSTANT): acc = bw1^T g1(scratch)
        APPLY16(ZERO_AC)
#undef ZERO_AC
#pragma unroll 1
        for (int i = 0; i < W; i++) {
            float v0, v1;
            unpk(pS[i * TPB], v0, v1);
            u64 d0 = dup2(v0), d1 = dup2(v1);
            ROWFMA2(cBW1 + i * 32, d0, d1);
        }

        // ---- dy = sum_k (pre0_k>0 ? w0y_k : 0) * g0raw_k
        float dy0 = 0.0f, dy1 = 0.0f;
#define DYM(p) {                                                           \
        float _al, _ah, _cl, _ch;                                          \
        unpk(A##p, _al, _ah); unpk(C##p, _cl, _ch);                        \
        float _wl = s_w0y[2 * p], _wh = s_w0y[2 * p + 1];                  \
        dy0 = fmaf((m0a & (1u << (2 * p)))     ? _wl : 0.0f, _al, dy0);    \
        dy0 = fmaf((m0a & (1u << (2 * p + 1))) ? _wh : 0.0f, _ah, dy0);    \
        dy1 = fmaf((m0b & (1u << (2 * p)))     ? _wl : 0.0f, _cl, dy1);    \
        dy1 = fmaf((m0b & (1u << (2 * p + 1))) ? _wh : 0.0f, _ch, dy1); }
        APPLY16(DYM)
#undef DYM

        y0 = fmaf(-INNER_LR, dy0, y0);
        y1 = fmaf(-INNER_LR, dy1, y1);
    }

    gOUT[s0] = y0;
    if (s1 < n) gOUT[s1] = y1;
}

extern "C" void kernel_launch(void* const* d_in, const int* in_sizes, int n_in,
                              void* d_out, int out_size) {
    const float* x  = (const float*)d_in[0];
    const float* w0 = (const float*)d_in[1];
    const float* b0 = (const float*)d_in[2];
    const float* w1 = (const float*)d_in[3];
    const float* b1 = (const float*)d_in[4];
    const float* w2 = (const float*)d_in[5];
    const float* b2 = (const float*)d_in[6];
    const float* w3 = (const float*)d_in[7];
    const float* ymean = (const float*)d_in[9];  // d_in[8] = b3 (unused)
    float* out = (float*)d_out;

    // Backward matrices are consumed in natural layout: copy verbatim into
    // constant memory. Async D2D memcpy -> graph-capturable memcpy nodes.
    cudaMemcpyToSymbolAsync(cBW1, w1, W * W * sizeof(float), 0,
                            cudaMemcpyDeviceToDevice);
    cudaMemcpyToSymbolAsync(cBW2, w2, W * W * sizeof(float), 0,
                            cudaMemcpyDeviceToDevice);

    int n = in_sizes[0];
    int blocks = (n + 2 * TPB - 1) / (2 * TPB);
    BaseEBM_kernel<<<blocks, TPB>>>(x, w0, b0, w1, b1, w2, b2, w3, ymean, out, n);
}

// round 15
// speedup vs baseline: 1.1926x; 1.0815x over previous
#include <cuda_runtime.h>

// BaseEBM: 1M samples x 20 GD steps on y through fixed 2->32->32->32->1
// ReLU MLP. R15 = R14 (manual software pipeline, half-row double buffer)
// with the macro token-pasting bug fixed: buffer registers are passed as
// EXPLICIT macro arguments (no ## pasting; `3.x` lexes as one pp-number so
// B##3.x is ill-formed). Theory unchanged: fma~70%/issue~68% plateau =
// per-row LDS->FFMA2 bubble; X/Y half-row buffers give each load >=32
// pipe-cyc of independent FFMA2 cover within the 128-reg cap.
// Backward matvecs on constant port; 2 samples/thread; f32x2.

#define W 32
#define INNER_STEPS 20
#define INNER_LR 0.1f
#define TPB 128

using u64 = unsigned long long;

__constant__ float cBW2[W * W];   // W2 natural: cBW2[i*32+j] = W2[i][j]
__constant__ float cBW1[W * W];   // W1 natural: cBW1[i*32+j] = W1[i][j]

__device__ __forceinline__ u64 fma2(u64 a, u64 b, u64 c) {
    u64 d;
    asm("fma.rn.f32x2 %0, %1, %2, %3;" : "=l"(d) : "l"(a), "l"(b), "l"(c));
    return d;
}
__device__ __forceinline__ u64 dup2(float x) {
    u64 d;
    asm("mov.b64 %0, {%1, %1};" : "=l"(d) : "f"(x));
    return d;
}
__device__ __forceinline__ u64 pack2(float lo, float hi) {
    u64 d;
    asm("mov.b64 %0, {%1, %2};" : "=l"(d) : "f"(lo), "f"(hi));
    return d;
}
__device__ __forceinline__ void unpk(u64 v, float& lo, float& hi) {
    asm("mov.b64 {%0, %1}, %2;" : "=f"(lo), "=f"(hi) : "l"(v));
}

#define APPLY16(M) M(0) M(1) M(2) M(3) M(4) M(5) M(6) M(7) \
                   M(8) M(9) M(10) M(11) M(12) M(13) M(14) M(15)

// Load one 64B half-row into the four named ulonglong2 regs (4x 128-bit ld).
#define LOADH(Q0, Q1, Q2, Q3, PTR) {                                       \
    const ulonglong2* _p = reinterpret_cast<const ulonglong2*>(PTR);       \
    Q0 = _p[0]; Q1 = _p[1]; Q2 = _p[2]; Q3 = _p[3]; }

// 16 FFMA2 on accumulator pairs 0..7 from buffer regs (low half of row).
#define HALF_LO(Q0, Q1, Q2, Q3, D0, D1)                                    \
    A0 = fma2(Q0.x, D0, A0); C0 = fma2(Q0.x, D1, C0);                      \
    A1 = fma2(Q0.y, D0, A1); C1 = fma2(Q0.y, D1, C1);                      \
    A2 = fma2(Q1.x, D0, A2); C2 = fma2(Q1.x, D1, C2);                      \
    A3 = fma2(Q1.y, D0, A3); C3 = fma2(Q1.y, D1, C3);                      \
    A4 = fma2(Q2.x, D0, A4); C4 = fma2(Q2.x, D1, C4);                      \
    A5 = fma2(Q2.y, D0, A5); C5 = fma2(Q2.y, D1, C5);                      \
    A6 = fma2(Q3.x, D0, A6); C6 = fma2(Q3.x, D1, C6);                      \
    A7 = fma2(Q3.y, D0, A7); C7 = fma2(Q3.y, D1, C7);

// 16 FFMA2 on accumulator pairs 8..15 from buffer regs (high half of row).
#define HALF_HI(Q0, Q1, Q2, Q3, D0, D1)                                    \
    A8  = fma2(Q0.x, D0, A8 ); C8  = fma2(Q0.x, D1, C8 );                  \
    A9  = fma2(Q0.y, D0, A9 ); C9  = fma2(Q0.y, D1, C9 );                  \
    A10 = fma2(Q1.x, D0, A10); C10 = fma2(Q1.x, D1, C10);                  \
    A11 = fma2(Q1.y, D0, A11); C11 = fma2(Q1.y, D1, C11);                  \
    A12 = fma2(Q2.x, D0, A12); C12 = fma2(Q2.x, D1, C12);                  \
    A13 = fma2(Q2.y, D0, A13); C13 = fma2(Q2.y, D1, C13);                  \
    A14 = fma2(Q3.x, D0, A14); C14 = fma2(Q3.x, D1, C14);                  \
    A15 = fma2(Q3.y, D0, A15); C15 = fma2(Q3.y, D1, C15);

__global__ __launch_bounds__(TPB, 4) void BaseEBM_kernel(
    const float* __restrict__ gX,
    const float* __restrict__ gW0,   // [32,2]
    const float* __restrict__ gB0,   // [32]
    const float* __restrict__ gW1,   // [32,32]
    const float* __restrict__ gB1,   // [32]
    const float* __restrict__ gW2,   // [32,32]
    const float* __restrict__ gB2,   // [32]
    const float* __restrict__ gW3,   // [32]
    const float* __restrict__ gYM,   // [1]
    float* __restrict__ gOUT,
    int n) {
    __shared__ alignas(16) float s_fw1[W * W];   // fw1[i*32+j] = W1[j][i]
    __shared__ alignas(16) float s_fw2[W * W];   // fw2[i*32+j] = W2[j][i]
    __shared__ alignas(16) float s_w0x[W];
    __shared__ alignas(16) float s_w0y[W];
    __shared__ alignas(16) float s_b0[W];
    __shared__ alignas(16) float s_b1[W];
    __shared__ alignas(16) float s_b2[W];
    __shared__ alignas(16) float s_w3[W];
    __shared__ alignas(16) u64 scr[W * TPB];  // per-thread col; 2 samples packed

    const int tid = threadIdx.x;
#pragma unroll
    for (int k = 0; k < (W * W) / TPB; k++) {
        int e = k * TPB + tid;
        int i = e >> 5, j = e & 31;
        s_fw1[e] = gW1[j * W + i];
        s_fw2[e] = gW2[j * W + i];
    }
    if (tid < W) {
        s_w0x[tid] = gW0[2 * tid + 0];
        s_w0y[tid] = gW0[2 * tid + 1];
        s_b0[tid]  = gB0[tid];
        s_b1[tid]  = gB1[tid];
        s_b2[tid]  = gB2[tid];
        s_w3[tid]  = gW3[tid];
    }
    __syncthreads();

    const int s0 = blockIdx.x * (2 * TPB) + tid;
    const int s1 = s0 + TPB;
    if (s0 >= n) return;

    const float x0 = gX[s0];
    const float x1 = (s1 < n) ? gX[s1] : 0.0f;
    float y0 = gYM[0];
    float y1 = y0;

    const u64* b1p = reinterpret_cast<const u64*>(s_b1);
    const u64* b2p = reinterpret_cast<const u64*>(s_b2);
    u64* pS = scr + tid;

    u64 A0, A1, A2, A3, A4, A5, A6, A7;
    u64 A8, A9, A10, A11, A12, A13, A14, A15;
    u64 C0, C1, C2, C3, C4, C5, C6, C7;
    u64 C8, C9, C10, C11, C12, C13, C14, C15;
    ulonglong2 X0, X1, X2, X3;   // weight half-row buffer A
    ulonglong2 Y0, Y1, Y2, Y3;   // weight half-row buffer B

#pragma unroll 1
    for (int s = 0; s < INNER_STEPS; s++) {
        unsigned m0a = 0u, m0b = 0u, m1a = 0u, m1b = 0u, m2a = 0u, m2b = 0u;

        // ==== matvec 1 (smem fw1): acc = b1 + fw1^T relu(pre0) =========
#define INIT_B1(p) { u64 _b = b1p[p]; A##p = _b; C##p = _b; }
        APPLY16(INIT_B1)
#undef INIT_B1
        {
            float wx = s_w0x[0], wy = s_w0y[0], bb = s_b0[0];
            LOADH(X0, X1, X2, X3, s_fw1)
#pragma unroll 1
            for (int i = 0; i < W; i++) {
                float pa = fmaf(y0, wy, fmaf(x0, wx, bb));
                float pb = fmaf(y1, wy, fmaf(x1, wx, bb));
                m0a |= (pa > 0.0f) ? (1u << i) : 0u;
                m0b |= (pb > 0.0f) ? (1u << i) : 0u;
                u64 d0 = dup2(fmaxf(pa, 0.0f));
                u64 d1 = dup2(fmaxf(pb, 0.0f));
                LOADH(Y0, Y1, Y2, Y3, s_fw1 + i * 32 + 16)   // hi half, row i
                int j = (i + 1) & 31;
                wx = s_w0x[j]; wy = s_w0y[j]; bb = s_b0[j];
                HALF_LO(X0, X1, X2, X3, d0, d1)              // covers Y
                LOADH(X0, X1, X2, X3, s_fw1 + j * 32)        // lo half, next row
                HALF_HI(Y0, Y1, Y2, Y3, d0, d1)              // covers X
            }
        }

        // ---- acc = pre1. h1 = relu -> scratch; m1 recorded.
#define ST_H1(p) {                                                         \
        float _al, _ah, _cl, _ch;                                          \
        unpk(A##p, _al, _ah); unpk(C##p, _cl, _ch);                        \
        m1a |= (_al > 0.0f) ? (1u << (2 * p))     : 0u;                    \
        m1a |= (_ah > 0.0f) ? (1u << (2 * p + 1)) : 0u;                    \
        m1b |= (_cl > 0.0f) ? (1u << (2 * p))     : 0u;                    \
        m1b |= (_ch > 0.0f) ? (1u << (2 * p + 1)) : 0u;                    \
        pS[(2 * p) * TPB]     = pack2(fmaxf(_al, 0.0f), fmaxf(_cl, 0.0f)); \
        pS[(2 * p + 1) * TPB] = pack2(fmaxf(_ah, 0.0f), fmaxf(_ch, 0.0f)); }
        APPLY16(ST_H1)
#undef ST_H1

        // ==== matvec 2 (smem fw2): acc = b2 + fw2^T h1(scratch) ========
#define INIT_B2(p) { u64 _b = b2p[p]; A##p = _b; C##p = _b; }
        APPLY16(INIT_B2)
#undef INIT_B2
        {
            u64 vcur = pS[0];
            LOADH(X0, X1, X2, X3, s_fw2)
#pragma unroll 1
            for (int i = 0; i < W; i++) {
                float v0, v1;
                unpk(vcur, v0, v1);
                u64 d0 = dup2(v0), d1 = dup2(v1);
                LOADH(Y0, Y1, Y2, Y3, s_fw2 + i * 32 + 16)
                int j = (i + 1) & 31;
                vcur = pS[j * TPB];
                HALF_LO(X0, X1, X2, X3, d0, d1)
                LOADH(X0, X1, X2, X3, s_fw2 + j * 32)
                HALF_HI(Y0, Y1, Y2, Y3, d0, d1)
            }
        }

        // ---- acc = pre2. Record sign masks only (g2 = m2 ? w3 : 0).
#define ST_M2(p) {                                                         \
        float _al, _ah, _cl, _ch;                                          \
        unpk(A##p, _al, _ah); unpk(C##p, _cl, _ch);                        \
        m2a |= (_al > 0.0f) ? (1u << (2 * p))     : 0u;                    \
        m2a |= (_ah > 0.0f) ? (1u << (2 * p + 1)) : 0u;                    \
        m2b |= (_cl > 0.0f) ? (1u << (2 * p))     : 0u;                    \
        m2b |= (_ch > 0.0f) ? (1u << (2 * p + 1)) : 0u; }
        APPLY16(ST_M2)
#undef ST_M2

        // ==== matvec 3 (constant bw2): acc = bw2^T (m2-masked w3) ======
#define ZERO_AC(p) { A##p = 0ull; C##p = 0ull; }
        APPLY16(ZERO_AC)
        {
            float w3c = s_w3[0];
            LOADH(X0, X1, X2, X3, cBW2)
#pragma unroll 1
            for (int i = 0; i < W; i++) {
                float ga = ((m2a >> i) & 1u) ? w3c : 0.0f;
                float gb = ((m2b >> i) & 1u) ? w3c : 0.0f;
                u64 d0 = dup2(ga), d1 = dup2(gb);
                LOADH(Y0, Y1, Y2, Y3, cBW2 + i * 32 + 16)
                int j = (i + 1) & 31;
                w3c = s_w3[j];
                HALF_LO(X0, X1, X2, X3, d0, d1)
                LOADH(X0, X1, X2, X3, cBW2 + j * 32)
                HALF_HI(Y0, Y1, Y2, Y3, d0, d1)
            }
        }

        // ---- acc = g1raw. g1 = m1-masked -> scratch.
#define ST_G1(p) {                                                         \
        float _al, _ah, _cl, _ch;                                          \
        unpk(A##p, _al, _ah); unpk(C##p, _cl, _ch);                        \
        pS[(2 * p) * TPB]     = pack2((m1a & (1u << (2 * p)))     ? _al : 0.0f, \
                                      (m1b & (1u << (2 * p)))     ? _cl : 0.0f); \
        pS[(2 * p + 1) * TPB] = pack2((m1a & (1u << (2 * p + 1))) ? _ah : 0.0f, \
                                      (m1b & (1u << (2 * p + 1))) ? _ch : 0.0f); }
        APPLY16(ST_G1)
#undef ST_G1

        // ==== matvec 4 (constant bw1): acc = bw1^T g1(scratch) =========
        APPLY16(ZERO_AC)
#undef ZERO_AC
        {
            u64 vcur = pS[0];
            LOADH(X0, X1, X2, X3, cBW1)
#pragma unroll 1
            for (int i = 0; i < W; i++) {
                float v0, v1;
                unpk(vcur, v0, v1);
                u64 d0 = dup2(v0), d1 = dup2(v1);
                LOADH(Y0, Y1, Y2, Y3, cBW1 + i * 32 + 16)
                int j = (i + 1) & 31;
                vcur = pS[j * TPB];
                HALF_LO(X0, X1, X2, X3, d0, d1)
                LOADH(X0, X1, X2, X3, cBW1 + j * 32)
                HALF_HI(Y0, Y1, Y2, Y3, d0, d1)
            }
        }

        // ---- dy = sum_k (pre0_k>0 ? w0y_k : 0) * g0raw_k
        float dy0 = 0.0f, dy1 = 0.0f;
#define DYM(p) {                                                           \
        float _al, _ah, _cl, _ch;                                          \
        unpk(A##p, _al, _ah); unpk(C##p, _cl, _ch);                        \
        float _wl = s_w0y[2 * p], _wh = s_w0y[2 * p + 1];                  \
        dy0 = fmaf((m0a & (1u << (2 * p)))     ? _wl : 0.0f, _al, dy0);    \
        dy0 = fmaf((m0a & (1u << (2 * p + 1))) ? _wh : 0.0f, _ah, dy0);    \
        dy1 = fmaf((m0b & (1u << (2 * p)))     ? _wl : 0.0f, _cl, dy1);    \
        dy1 = fmaf((m0b & (1u << (2 * p + 1))) ? _wh : 0.0f, _ch, dy1); }
        APPLY16(DYM)
#undef DYM

        y0 = fmaf(-INNER_LR, dy0, y0);
        y1 = fmaf(-INNER_LR, dy1, y1);
    }

    gOUT[s0] = y0;
    if (s1 < n) gOUT[s1] = y1;
}

extern "C" void kernel_launch(void* const* d_in, const int* in_sizes, int n_in,
                              void* d_out, int out_size) {
    const float* x  = (const float*)d_in[0];
    const float* w0 = (const float*)d_in[1];
    const float* b0 = (const float*)d_in[2];
    const float* w1 = (const float*)d_in[3];
    const float* b1 = (const float*)d_in[4];
    const float* w2 = (const float*)d_in[5];
    const float* b2 = (const float*)d_in[6];
    const float* w3 = (const float*)d_in[7];
    const float* ymean = (const float*)d_in[9];  // d_in[8] = b3 (unused)
    float* out = (float*)d_out;

    // Backward matrices consumed in natural layout -> constant memory.
    // Async D2D memcpys are graph-capturable nodes.
    cudaMemcpyToSymbolAsync(cBW1, w1, W * W * sizeof(float), 0,
                            cudaMemcpyDeviceToDevice);
    cudaMemcpyToSymbolAsync(cBW2, w2, W * W * sizeof(float), 0,
                            cudaMemcpyDeviceToDevice);

    int n = in_sizes[0];
    int blocks = (n + 2 * TPB - 1) / (2 * TPB);
    BaseEBM_kernel<<<blocks, TPB>>>(x, w0, b0, w1, b1, w2, b2, w3, ymean, out, n);
}